// round 11
// baseline (speedup 1.0000x reference)
#include <cuda_runtime.h>

// 3D Haar DWT, level 1, x [B=2, C=32, D=64, H=128, W=128] f32
// -> out [B, 8C, D/2, H/2, W/2], subband order aaa,aad,ada,add,daa,dad,dda,ddd
// (bits: depth,height,width; channel = sb*C + c).
//
// R10: R1 per-thread code (best measured: 74.3us, 6.5TB/s) with 128-thread
// CTAs (32768 blocks) — finer CTA scheduling granularity, 2x resident CTAs,
// smaller per-CTA LDG bursts into the LTS queues. Bandwidth analysis: achieved
// 6455 GB/s == LTS cap (6300 B/cyc) at the sustained clock; traffic is minimal
// (512 MB, each byte once through L2 each way), so launch geometry is the only
// remaining free axis.

#define B_   2
#define C_   32
#define D_   64
#define H_   128
#define W_   128
#define DH   (D_/2)
#define HH   (H_/2)
#define WH   (W_/2)
#define WQ   (W_/4)   // thread handles 2 output-w positions (4 input w)

__global__ void __launch_bounds__(128) haar3d_kernel(
    const float* __restrict__ x, float* __restrict__ out)
{
    const float K = 0.35355339059327373f;  // (1/sqrt(2))^3

    int t = blockIdx.x * blockDim.x + threadIdx.x;
    // t = ((((b*C + c)*DH + dz)*HH + dy)*WQ + wq)
    int wq =  t        & (WQ - 1);         // 0..31
    int dy = (t >> 5)  & (HH - 1);         // 0..63
    int dz = (t >> 11) & (DH - 1);         // 0..31
    int c  = (t >> 16) & (C_ - 1);         // 0..31
    int b  =  t >> 21;                     // 0..1

    // ---- input loads: 4 rows x float4, front-batched ----
    size_t ibase = ((((size_t)(b * C_ + c) * D_ + 2 * dz) * H_ + 2 * dy) * W_) + 4 * wq;
    const float4 r00 = *(const float4*)(x + ibase);                         // d=0, h=0
    const float4 r01 = *(const float4*)(x + ibase + W_);                    // d=0, h=1
    const float4 r10 = *(const float4*)(x + ibase + (size_t)H_ * W_);       // d=1, h=0
    const float4 r11 = *(const float4*)(x + ibase + (size_t)H_ * W_ + W_);  // d=1, h=1

    // ---- width stage: two cubes, p=0 (.x,.y) p=1 (.z,.w) ----
    float wl00a = r00.x + r00.y, wh00a = r00.x - r00.y;  // cube 0
    float wl01a = r01.x + r01.y, wh01a = r01.x - r01.y;
    float wl10a = r10.x + r10.y, wh10a = r10.x - r10.y;
    float wl11a = r11.x + r11.y, wh11a = r11.x - r11.y;

    float wl00b = r00.z + r00.w, wh00b = r00.z - r00.w;  // cube 1
    float wl01b = r01.z + r01.w, wh01b = r01.z - r01.w;
    float wl10b = r10.z + r10.w, wh10b = r10.z - r10.w;
    float wl11b = r11.z + r11.w, wh11b = r11.z - r11.w;

    // ---- height + depth stages, scale; sb = 4*d_hp + 2*h_hp + w_hp ----
    float s0[8], s1[8];
    {
        float hl_l0 = wl00a + wl01a, hh_l0 = wl00a - wl01a;  // d0, w-low
        float hl_h0 = wh00a + wh01a, hh_h0 = wh00a - wh01a;  // d0, w-high
        float hl_l1 = wl10a + wl11a, hh_l1 = wl10a - wl11a;  // d1
        float hl_h1 = wh10a + wh11a, hh_h1 = wh10a - wh11a;
        s0[0] = (hl_l0 + hl_l1) * K;  // aaa
        s0[1] = (hl_h0 + hl_h1) * K;  // aad
        s0[2] = (hh_l0 + hh_l1) * K;  // ada
        s0[3] = (hh_h0 + hh_h1) * K;  // add
        s0[4] = (hl_l0 - hl_l1) * K;  // daa
        s0[5] = (hl_h0 - hl_h1) * K;  // dad
        s0[6] = (hh_l0 - hh_l1) * K;  // dda
        s0[7] = (hh_h0 - hh_h1) * K;  // ddd
    }
    {
        float hl_l0 = wl00b + wl01b, hh_l0 = wl00b - wl01b;
        float hl_h0 = wh00b + wh01b, hh_h0 = wh00b - wh01b;
        float hl_l1 = wl10b + wl11b, hh_l1 = wl10b - wl11b;
        float hl_h1 = wh10b + wh11b, hh_h1 = wh10b - wh11b;
        s1[0] = (hl_l0 + hl_l1) * K;
        s1[1] = (hl_h0 + hl_h1) * K;
        s1[2] = (hh_l0 + hh_l1) * K;
        s1[3] = (hh_h0 + hh_h1) * K;
        s1[4] = (hl_l0 - hl_l1) * K;
        s1[5] = (hl_h0 - hl_h1) * K;
        s1[6] = (hh_l0 - hh_l1) * K;
        s1[7] = (hh_h0 - hh_h1) * K;
    }

    // ---- output: channel = sb*C + c ; float2 per subband ----
    size_t obase = ((((size_t)(b * 8 * C_ + c) * DH + dz) * HH + dy) * WH) + 2 * wq;
    const size_t sbStride = (size_t)C_ * DH * HH * WH;  // sb advances 32 channels

#pragma unroll
    for (int sb = 0; sb < 8; sb++) {
        *(float2*)(out + obase + (size_t)sb * sbStride) = make_float2(s0[sb], s1[sb]);
    }
}

extern "C" void kernel_launch(void* const* d_in, const int* in_sizes, int n_in,
                              void* d_out, int out_size) {
    const float* x = (const float*)d_in[0];
    float* out = (float*)d_out;
    // total threads = B*C*DH*HH*WQ = 2*32*32*64*32 = 4,194,304
    const int total = B_ * C_ * DH * HH * WQ;
    haar3d_kernel<<<total / 128, 128>>>(x, out);
}

// round 12
// speedup vs baseline: 1.0082x; 1.0082x over previous
#include <cuda_runtime.h>

// 3D Haar DWT, level 1, x [B=2, C=32, D=64, H=128, W=128] f32
// -> out [B, 8C, D/2, H/2, W/2], subband order aaa,aad,ada,add,daa,dad,dda,ddd
// (bits: depth,height,width; channel = sb*C + c).
//
// FINAL — R1 configuration, best measured: 74.3us kernel, 6.52 TB/s,
// DRAM 82.2%. One thread = two adjacent 2x2x2 cubes along W: 4x front-batched
// LDG.128 in, 8x STG.64 out (one per subband stream). Flat 16384x256 launch.
//
// Closed search (R2-R10): MLP depth 4/8/16, widths 64/128/256-bit, .cs hints,
// smem-staged subband-segregated stores, persistent grid-stride, 128-thread
// CTAs — all neutral or worse. Achieved BW == LTS chip cap (~6300 B/cyc,
// path-independent) at sustained clock; traffic is minimal (512 MB, each byte
// through L2 once per direction). This is the hardware floor for this op.

#define B_   2
#define C_   32
#define D_   64
#define H_   128
#define W_   128
#define DH   (D_/2)
#define HH   (H_/2)
#define WH   (W_/2)
#define WQ   (W_/4)   // thread handles 2 output-w positions (4 input w)

__global__ void __launch_bounds__(256) haar3d_kernel(
    const float* __restrict__ x, float* __restrict__ out)
{
    const float K = 0.35355339059327373f;  // (1/sqrt(2))^3

    int t = blockIdx.x * blockDim.x + threadIdx.x;
    // t = ((((b*C + c)*DH + dz)*HH + dy)*WQ + wq)
    int wq =  t        & (WQ - 1);         // 0..31
    int dy = (t >> 5)  & (HH - 1);         // 0..63
    int dz = (t >> 11) & (DH - 1);         // 0..31
    int c  = (t >> 16) & (C_ - 1);         // 0..31
    int b  =  t >> 21;                     // 0..1

    // ---- input loads: 4 rows x float4, front-batched ----
    size_t ibase = ((((size_t)(b * C_ + c) * D_ + 2 * dz) * H_ + 2 * dy) * W_) + 4 * wq;
    const float4 r00 = *(const float4*)(x + ibase);                         // d=0, h=0
    const float4 r01 = *(const float4*)(x + ibase + W_);                    // d=0, h=1
    const float4 r10 = *(const float4*)(x + ibase + (size_t)H_ * W_);       // d=1, h=0
    const float4 r11 = *(const float4*)(x + ibase + (size_t)H_ * W_ + W_);  // d=1, h=1

    // ---- width stage: two cubes, p=0 (.x,.y) p=1 (.z,.w) ----
    float wl00a = r00.x + r00.y, wh00a = r00.x - r00.y;  // cube 0
    float wl01a = r01.x + r01.y, wh01a = r01.x - r01.y;
    float wl10a = r10.x + r10.y, wh10a = r10.x - r10.y;
    float wl11a = r11.x + r11.y, wh11a = r11.x - r11.y;

    float wl00b = r00.z + r00.w, wh00b = r00.z - r00.w;  // cube 1
    float wl01b = r01.z + r01.w, wh01b = r01.z - r01.w;
    float wl10b = r10.z + r10.w, wh10b = r10.z - r10.w;
    float wl11b = r11.z + r11.w, wh11b = r11.z - r11.w;

    // ---- height + depth stages, scale; sb = 4*d_hp + 2*h_hp + w_hp ----
    float s0[8], s1[8];
    {
        float hl_l0 = wl00a + wl01a, hh_l0 = wl00a - wl01a;  // d0, w-low
        float hl_h0 = wh00a + wh01a, hh_h0 = wh00a - wh01a;  // d0, w-high
        float hl_l1 = wl10a + wl11a, hh_l1 = wl10a - wl11a;  // d1
        float hl_h1 = wh10a + wh11a, hh_h1 = wh10a - wh11a;
        s0[0] = (hl_l0 + hl_l1) * K;  // aaa
        s0[1] = (hl_h0 + hl_h1) * K;  // aad
        s0[2] = (hh_l0 + hh_l1) * K;  // ada
        s0[3] = (hh_h0 + hh_h1) * K;  // add
        s0[4] = (hl_l0 - hl_l1) * K;  // daa
        s0[5] = (hl_h0 - hl_h1) * K;  // dad
        s0[6] = (hh_l0 - hh_l1) * K;  // dda
        s0[7] = (hh_h0 - hh_h1) * K;  // ddd
    }
    {
        float hl_l0 = wl00b + wl01b, hh_l0 = wl00b - wl01b;
        float hl_h0 = wh00b + wh01b, hh_h0 = wh00b - wh01b;
        float hl_l1 = wl10b + wl11b, hh_l1 = wl10b - wl11b;
        float hl_h1 = wh10b + wh11b, hh_h1 = wh10b - wh11b;
        s1[0] = (hl_l0 + hl_l1) * K;
        s1[1] = (hl_h0 + hl_h1) * K;
        s1[2] = (hh_l0 + hh_l1) * K;
        s1[3] = (hh_h0 + hh_h1) * K;
        s1[4] = (hl_l0 - hl_l1) * K;
        s1[5] = (hl_h0 - hl_h1) * K;
        s1[6] = (hh_l0 - hh_l1) * K;
        s1[7] = (hh_h0 - hh_h1) * K;
    }

    // ---- output: channel = sb*C + c ; float2 per subband ----
    size_t obase = ((((size_t)(b * 8 * C_ + c) * DH + dz) * HH + dy) * WH) + 2 * wq;
    const size_t sbStride = (size_t)C_ * DH * HH * WH;  // sb advances 32 channels

#pragma unroll
    for (int sb = 0; sb < 8; sb++) {
        *(float2*)(out + obase + (size_t)sb * sbStride) = make_float2(s0[sb], s1[sb]);
    }
}

extern "C" void kernel_launch(void* const* d_in, const int* in_sizes, int n_in,
                              void* d_out, int out_size) {
    const float* x = (const float*)d_in[0];
    float* out = (float*)d_out;
    // total threads = B*C*DH*HH*WQ = 2*32*32*64*32 = 4,194,304
    const int total = B_ * C_ * DH * HH * WQ;
    haar3d_kernel<<<total / 256, 256>>>(x, out);
}